// round 7
// baseline (speedup 1.0000x reference)
#include <cuda_runtime.h>
#include <cstdint>

// ---------------------------------------------------------------------------
//   q [4,2048,1024], c [4,2048,1024], W_kv [1024,2048], b_kv [2048],
//   W_o [1024,1024], b_o [1024] -> out [4,2048,1024] fp32
// kv row layout per (b,s): head h -> K at cols h*128..+63, V at h*128+64..+127
// ---------------------------------------------------------------------------

#define BATCH 4
#define SEQ   2048
#define EMB   1024
#define NH    16
#define HD    64

__device__ float g_kv[(size_t)BATCH * SEQ * 2 * EMB];    // 64 MB
__device__ float g_vals[(size_t)BATCH * SEQ * EMB];      // 32 MB
__device__ float g_wkvt[(size_t)2 * EMB * EMB];          // 8 MB  W_kv^T [2048,1024]
__device__ float g_wot[(size_t)EMB * EMB];               // 4 MB  W_o^T  [1024,1024]

__device__ __forceinline__ uint32_t f2tf(float x) {
    uint32_t r;
    asm("cvt.rna.tf32.f32 %0, %1;" : "=r"(r) : "f"(x));
    return r;
}
__device__ __forceinline__ float ex2f(float x) {
    float y;
    asm("ex2.approx.f32 %0, %1;" : "=f"(y) : "f"(x));
    return y;
}

#define MMA_TF32(d, a, b0v, b1v)                                            \
    asm volatile("mma.sync.aligned.m16n8k8.row.col.f32.tf32.tf32.f32 "      \
        "{%0,%1,%2,%3}, {%4,%5,%6,%7}, {%8,%9}, {%0,%1,%2,%3};"             \
        : "+f"((d)[0]), "+f"((d)[1]), "+f"((d)[2]), "+f"((d)[3])            \
        : "r"((a)[0]), "r"((a)[1]), "r"((a)[2]), "r"((a)[3]),               \
          "r"(b0v), "r"(b1v))

// ======================= weight transpose ===================================
__global__ __launch_bounds__(256)
void transpose_kernel(const float* __restrict__ in, float* __restrict__ out,
                      int R, int C)
{
    __shared__ float t[32][33];
    int bx = blockIdx.x * 32, by = blockIdx.y * 32;
    int x = bx + threadIdx.x;
    #pragma unroll
    for (int i = 0; i < 32; i += 8)
        t[threadIdx.y + i][threadIdx.x] = in[(size_t)(by + threadIdx.y + i) * C + x];
    __syncthreads();
    int ox = by + threadIdx.x;
    #pragma unroll
    for (int i = 0; i < 32; i += 8)
        out[(size_t)(bx + threadIdx.y + i) * R + ox] = t[threadIdx.x][threadIdx.y + i];
}

// ======================= raw-mma tf32 GEMM + bias (pair-packed, 2 CTA/SM) ===
// C[M,N] = A[M,K] @ Bt[N,K]^T + bias[N].  Block 128x128, 8 warps.
// smem tiles pair-packed: within each 8-col K group, cols stored as pairs
// (t, t+4) so an mma B/A fragment is one LDS.64. Row stride 40 (==8 mod 32:
// (8g+2qd) conflict-free across half-warp).
#define GLD 40
#define GASZ (128 * GLD)          // 5120 words per A (or B) buffer
#define GSMEM (4 * GASZ * 4)      // 81920 bytes

__global__ __launch_bounds__(256, 2)
void gemm_mma_tf32(const float* __restrict__ A, const float* __restrict__ Bt,
                   const float* __restrict__ bias, float* __restrict__ C,
                   int M, int N, int K)
{
    extern __shared__ uint32_t gsm[];
    // layout: As[2][GASZ] | Bs[2][GASZ]

    const int tid  = threadIdx.x;
    const int w    = tid >> 5;
    const int lane = tid & 31;
    const int g    = lane >> 2;
    const int qd   = lane & 3;
    const int brow = blockIdx.y * 128;
    const int bcol = blockIdx.x * 128;

    float acc[16][4];
    #pragma unroll
    for (int j = 0; j < 16; j++)
        #pragma unroll
        for (int e = 0; e < 4; e++) acc[j][e] = 0.f;

    const int lr = tid >> 1;          // 0..127
    const int lc = (tid & 1) * 16;    // 0 or 16

    float4 Ar[4], Br[4];
    auto LOADT = [&](int k0) {
        const float* ap = A  + (size_t)(brow + lr) * K + k0 + lc;
        const float* bp = Bt + (size_t)(bcol + lr) * K + k0 + lc;
        #pragma unroll
        for (int i = 0; i < 4; i++) {
            Ar[i] = *(const float4*)(ap + 4 * i);
            Br[i] = *(const float4*)(bp + 4 * i);
        }
    };
    auto STORET = [&](int p) {
        uint32_t* Ab = gsm + p * GASZ;
        uint32_t* Bb = gsm + 2 * GASZ + p * GASZ;
        float ax[16] = {Ar[0].x,Ar[0].y,Ar[0].z,Ar[0].w, Ar[1].x,Ar[1].y,Ar[1].z,Ar[1].w,
                        Ar[2].x,Ar[2].y,Ar[2].z,Ar[2].w, Ar[3].x,Ar[3].y,Ar[3].z,Ar[3].w};
        float bx[16] = {Br[0].x,Br[0].y,Br[0].z,Br[0].w, Br[1].x,Br[1].y,Br[1].z,Br[1].w,
                        Br[2].x,Br[2].y,Br[2].z,Br[2].w, Br[3].x,Br[3].y,Br[3].z,Br[3].w};
        #pragma unroll
        for (int gi = 0; gi < 2; gi++) {
            int colb = lr * GLD + lc + 8 * gi;
            #pragma unroll
            for (int t = 0; t < 4; t++) {
                uint2 ua, ub;
                ua.x = f2tf(ax[8 * gi + t]); ua.y = f2tf(ax[8 * gi + t + 4]);
                ub.x = f2tf(bx[8 * gi + t]); ub.y = f2tf(bx[8 * gi + t + 4]);
                *(uint2*)&Ab[colb + 2 * t] = ua;
                *(uint2*)&Bb[colb + 2 * t] = ub;
            }
        }
    };

    LOADT(0);
    STORET(0);
    __syncthreads();

    const int arow0 = (16 * w + g) * GLD;
    const int arow1 = arow0 + 8 * GLD;

    const int NCH = K / 32;
    for (int ch = 0; ch < NCH; ch++) {
        const int p = ch & 1;
        if (ch + 1 < NCH) LOADT((ch + 1) * 32);

        const uint32_t* Ab = gsm + p * GASZ;
        const uint32_t* Bb = gsm + 2 * GASZ + p * GASZ;

        #pragma unroll
        for (int ks = 0; ks < 4; ks++) {
            uint2 a0 = *(const uint2*)&Ab[arow0 + 8 * ks + 2 * qd];
            uint2 a1 = *(const uint2*)&Ab[arow1 + 8 * ks + 2 * qd];
            uint32_t af[4] = {a0.x, a1.x, a0.y, a1.y};
            #pragma unroll
            for (int j = 0; j < 16; j++) {
                uint2 bb = *(const uint2*)&Bb[(8 * j + g) * GLD + 8 * ks + 2 * qd];
                MMA_TF32(acc[j], af, bb.x, bb.y);
            }
        }

        if (ch + 1 < NCH) STORET(1 - p);
        __syncthreads();
    }

    const int row0 = brow + 16 * w + g;
    const int row1 = row0 + 8;
    #pragma unroll
    for (int j = 0; j < 16; j++) {
        int col = bcol + 8 * j + 2 * qd;
        float b0 = __ldg(bias + col), b1 = __ldg(bias + col + 1);
        float2 x0 = make_float2(acc[j][0] + b0, acc[j][1] + b1);
        float2 x1 = make_float2(acc[j][2] + b0, acc[j][3] + b1);
        *(float2*)&C[(size_t)row0 * N + col] = x0;
        *(float2*)&C[(size_t)row1 * N + col] = x1;
    }
}

// ======================= Flash attention (pair-packed, 2 CTAs/SM) ===========
// Block: 128-row Q tile of one (b,h). KV tile 32 rows, double-buffered.
// K: row-major, cols packed in (t,t+4) pairs, stride 72 -> one LDS.64/frag.
// V: row-pairs (r, r+4) interleaved per column; group stride 136.
#define LDK2 72
#define KSZ2 (32 * LDK2)          // 2304 words
#define VQ   136
#define VKK  (4 * VQ)             // 544
#define VSZ2 (4 * VKK)            // 2176 words
#define STG2 (KSZ2 + VSZ2)        // 4480 words (17920 B)

__global__ __launch_bounds__(256, 2)
void flash_attn_mma(const float* __restrict__ q,
                    const float* __restrict__ kv,
                    float* __restrict__ vals)
{
    extern __shared__ uint32_t smx[];

    const int tid  = threadIdx.x;
    const int w    = tid >> 5;
    const int lane = tid & 31;
    const int g    = lane >> 2;
    const int qd   = lane & 3;
    const int b    = blockIdx.y >> 4;
    const int h    = blockIdx.y & 15;
    const int q0   = blockIdx.x * 128;

    const size_t qrow0 = (size_t)b * SEQ + q0 + w * 16;
    const float* qb = q + qrow0 * EMB + h * HD;

    // Q fragments, scaled by 1/8 * log2(e)  (softmax runs in exp2 domain)
    const float QS = 0.125f * 1.4426950408889634f;
    uint32_t qf[8][4];
    #pragma unroll
    for (int kk = 0; kk < 8; kk++) {
        qf[kk][0] = f2tf(qb[(size_t)g * EMB + 8 * kk + qd] * QS);
        qf[kk][1] = f2tf(qb[(size_t)(g + 8) * EMB + 8 * kk + qd] * QS);
        qf[kk][2] = f2tf(qb[(size_t)g * EMB + 8 * kk + qd + 4] * QS);
        qf[kk][3] = f2tf(qb[(size_t)(g + 8) * EMB + 8 * kk + qd + 4] * QS);
    }

    float oa[8][4];
    #pragma unroll
    for (int j = 0; j < 8; j++)
        #pragma unroll
        for (int e = 0; e < 4; e++) oa[j][e] = 0.f;
    float m0 = -1e30f, m1 = -1e30f, l0 = 0.f, l1 = 0.f;

    const float* kb = kv + (size_t)b * SEQ * (2 * EMB) + h * (2 * HD);

    // loader roles: threads 0-127 load K (row, 16 cols); 128-255 load V
    // (row-pair r,r+4, 8 cols each)
    const int ktRow = tid >> 2;            // 0..31 (K role)
    const int ktC   = (tid & 3) * 16;      // 0,16,32,48
    const int vtid  = tid - 128;
    const int vRp   = (vtid >> 3) & 15;    // 0..15
    const int vKKi  = vRp >> 2;            // 0..3
    const int vQd   = vRp & 3;
    const int vR0   = 8 * vKKi + vQd;
    const int vC    = (vtid & 7) * 8;      // 0..56

    float4 pv4[4];
    auto LOADT = [&](int it) {
        if (tid < 128) {
            const float* base = kb + (size_t)(it * 32 + ktRow) * (2 * EMB) + ktC;
            #pragma unroll
            for (int i = 0; i < 4; i++) pv4[i] = *(const float4*)(base + 4 * i);
        } else {
            const float* b0p = kb + (size_t)(it * 32 + vR0) * (2 * EMB) + HD + vC;
            const float* b1p = kb + (size_t)(it * 32 + vR0 + 4) * (2 * EMB) + HD + vC;
            pv4[0] = *(const float4*)b0p;
            pv4[1] = *(const float4*)(b0p + 4);
            pv4[2] = *(const float4*)b1p;
            pv4[3] = *(const float4*)(b1p + 4);
        }
    };
    auto STORET = [&](int s) {
        uint32_t* Ks = smx + s * STG2;
        uint32_t* Vp = Ks + KSZ2;
        if (tid < 128) {
            float x[16] = {pv4[0].x,pv4[0].y,pv4[0].z,pv4[0].w,
                           pv4[1].x,pv4[1].y,pv4[1].z,pv4[1].w,
                           pv4[2].x,pv4[2].y,pv4[2].z,pv4[2].w,
                           pv4[3].x,pv4[3].y,pv4[3].z,pv4[3].w};
            #pragma unroll
            for (int gi = 0; gi < 2; gi++) {
                int base = ktRow * LDK2 + ktC + 8 * gi;
                #pragma unroll
                for (int t = 0; t < 4; t++) {
                    uint2 u;
                    u.x = f2tf(x[8 * gi + t]);
                    u.y = f2tf(x[8 * gi + t + 4]);
                    *(uint2*)&Ks[base + 2 * t] = u;
                }
            }
        } else {
            float lo[8] = {pv4[0].x,pv4[0].y,pv4[0].z,pv4[0].w,
                           pv4[1].x,pv4[1].y,pv4[1].z,pv4[1].w};
            float hi[8] = {pv4[2].x,pv4[2].y,pv4[2].z,pv4[2].w,
                           pv4[3].x,pv4[3].y,pv4[3].z,pv4[3].w};
            int base = vKKi * VKK + vQd * VQ + vC * 2;
            #pragma unroll
            for (int cp = 0; cp < 4; cp++) {
                uint4 u;
                u.x = f2tf(lo[2 * cp]);     u.y = f2tf(hi[2 * cp]);
                u.z = f2tf(lo[2 * cp + 1]); u.w = f2tf(hi[2 * cp + 1]);
                *(uint4*)&Vp[base + 4 * cp] = u;
            }
        }
    };

    LOADT(0);
    STORET(0);
    __syncthreads();

    const int NIT = SEQ / 32;
    for (int it = 0; it < NIT; it++) {
        const int s = it & 1;
        const uint32_t* Ks = smx + s * STG2;
        const uint32_t* Vp = Ks + KSZ2;

        // ---- S = Q @ K^T : 4 kv n-tiles (LDS.64 fragments) ----
        float sa[4][4];
        #pragma unroll
        for (int j = 0; j < 4; j++)
            #pragma unroll
            for (int e = 0; e < 4; e++) sa[j][e] = 0.f;
        #pragma unroll
        for (int kk = 0; kk < 8; kk++) {
            #pragma unroll
            for (int j = 0; j < 4; j++) {
                uint2 bb = *(const uint2*)&Ks[(8 * j + g) * LDK2 + 8 * kk + 2 * qd];
                MMA_TF32(sa[j], qf[kk], bb.x, bb.y);
            }
        }

        // prefetch next KV tile
        if (it < NIT - 1) LOADT(it + 1);

        // ---- online softmax in exp2 domain ----
        float tm0 = -1e30f, tm1 = -1e30f;
        #pragma unroll
        for (int j = 0; j < 4; j++) {
            tm0 = fmaxf(tm0, fmaxf(sa[j][0], sa[j][1]));
            tm1 = fmaxf(tm1, fmaxf(sa[j][2], sa[j][3]));
        }
        tm0 = fmaxf(tm0, __shfl_xor_sync(0xffffffffu, tm0, 1));
        tm0 = fmaxf(tm0, __shfl_xor_sync(0xffffffffu, tm0, 2));
        tm1 = fmaxf(tm1, __shfl_xor_sync(0xffffffffu, tm1, 1));
        tm1 = fmaxf(tm1, __shfl_xor_sync(0xffffffffu, tm1, 2));
        float mn0 = fmaxf(m0, tm0), mn1 = fmaxf(m1, tm1);
        float al0 = ex2f(m0 - mn0), al1 = ex2f(m1 - mn1);
        m0 = mn0; m1 = mn1;

        uint32_t pf[4][4];
        float sum0 = 0.f, sum1 = 0.f;
        #pragma unroll
        for (int j = 0; j < 4; j++) {
            float p0 = ex2f(sa[j][0] - mn0);
            float p1 = ex2f(sa[j][1] - mn0);
            float p2 = ex2f(sa[j][2] - mn1);
            float p3 = ex2f(sa[j][3] - mn1);
            sum0 += p0 + p1; sum1 += p2 + p3;
            pf[j][0] = f2tf(p0); pf[j][1] = f2tf(p1);
            pf[j][2] = f2tf(p2); pf[j][3] = f2tf(p3);
        }
        l0 = l0 * al0 + sum0;
        l1 = l1 * al1 + sum1;
        #pragma unroll
        for (int j = 0; j < 8; j++) {
            oa[j][0] *= al0; oa[j][1] *= al0;
            oa[j][2] *= al1; oa[j][3] *= al1;
        }

        // ---- O += P @ V (LDS.64 fragments from row-pair layout) ----
        const int srcA = (lane & ~3) | (qd >> 1);
        const int srcB = srcA + 2;
        #pragma unroll
        for (int kk = 0; kk < 4; kk++) {
            uint32_t v0 = __shfl_sync(0xffffffffu, pf[kk][0], srcA);
            uint32_t v1 = __shfl_sync(0xffffffffu, pf[kk][1], srcA);
            uint32_t w0 = __shfl_sync(0xffffffffu, pf[kk][0], srcB);
            uint32_t w1 = __shfl_sync(0xffffffffu, pf[kk][1], srcB);
            uint32_t v2 = __shfl_sync(0xffffffffu, pf[kk][2], srcA);
            uint32_t v3 = __shfl_sync(0xffffffffu, pf[kk][3], srcA);
            uint32_t w2 = __shfl_sync(0xffffffffu, pf[kk][2], srcB);
            uint32_t w3 = __shfl_sync(0xffffffffu, pf[kk][3], srcB);
            uint32_t af[4];
            af[0] = (qd & 1) ? v1 : v0;
            af[2] = (qd & 1) ? w1 : w0;
            af[1] = (qd & 1) ? v3 : v2;
            af[3] = (qd & 1) ? w3 : w2;
            const int vbase = kk * VKK + qd * VQ;
            #pragma unroll
            for (int j = 0; j < 8; j++) {
                uint2 vv = *(const uint2*)&Vp[vbase + (8 * j + g) * 2];
                MMA_TF32(oa[j], af, vv.x, vv.y);
            }
        }

        if (it < NIT - 1) STORET(1 - s);
        __syncthreads();
    }

    // ---- epilogue ----
    l0 += __shfl_xor_sync(0xffffffffu, l0, 1);
    l0 += __shfl_xor_sync(0xffffffffu, l0, 2);
    l1 += __shfl_xor_sync(0xffffffffu, l1, 1);
    l1 += __shfl_xor_sync(0xffffffffu, l1, 2);
    float li0 = 1.0f / l0, li1 = 1.0f / l1;

    float* ob = vals + qrow0 * EMB + h * HD;
    #pragma unroll
    for (int j = 0; j < 8; j++) {
        float2 x0 = make_float2(oa[j][0] * li0, oa[j][1] * li0);
        float2 x1 = make_float2(oa[j][2] * li1, oa[j][3] * li1);
        *(float2*)&ob[(size_t)g * EMB + 8 * j + 2 * qd]       = x0;
        *(float2*)&ob[(size_t)(g + 8) * EMB + 8 * j + 2 * qd] = x1;
    }
}

// ======================= launch =============================================
extern "C" void kernel_launch(void* const* d_in, const int* in_sizes, int n_in,
                              void* d_out, int out_size)
{
    const float* q_in = (const float*)d_in[0];
    const float* c_in = (const float*)d_in[1];
    const float* Wkv  = (const float*)d_in[2];
    const float* bkv  = (const float*)d_in[3];
    const float* Wo   = (const float*)d_in[4];
    const float* bo   = (const float*)d_in[5];
    float* out = (float*)d_out;

    float *kv_ptr, *vals_ptr, *wkvt_ptr, *wot_ptr;
    cudaGetSymbolAddress((void**)&kv_ptr,  g_kv);
    cudaGetSymbolAddress((void**)&vals_ptr, g_vals);
    cudaGetSymbolAddress((void**)&wkvt_ptr, g_wkvt);
    cudaGetSymbolAddress((void**)&wot_ptr,  g_wot);

    const int M = BATCH * SEQ;             // 8192

    // 0) transpose weights
    transpose_kernel<<<dim3((2 * EMB) / 32, EMB / 32), dim3(32, 8)>>>(
        Wkv, wkvt_ptr, EMB, 2 * EMB);
    transpose_kernel<<<dim3(EMB / 32, EMB / 32), dim3(32, 8)>>>(
        Wo, wot_ptr, EMB, EMB);

    // 1) kv = c @ W_kv + b_kv         [8192, 2048]
    cudaFuncSetAttribute(gemm_mma_tf32,
                         cudaFuncAttributeMaxDynamicSharedMemorySize, GSMEM);
    gemm_mma_tf32<<<dim3((2 * EMB) / 128, M / 128), 256, GSMEM>>>(
        c_in, wkvt_ptr, bkv, kv_ptr, M, 2 * EMB, EMB);

    // 2) flash attention -> values    [8192, 1024]
    size_t smem = (size_t)2 * STG2 * sizeof(uint32_t);   // 35840 B
    cudaFuncSetAttribute(flash_attn_mma,
                         cudaFuncAttributeMaxDynamicSharedMemorySize, (int)smem);
    flash_attn_mma<<<dim3(SEQ / 128, BATCH * NH), 256, smem>>>(
        q_in, kv_ptr, vals_ptr);

    // 3) out = values @ W_o + b_o     [8192, 1024]
    gemm_mma_tf32<<<dim3(EMB / 128, M / 128), 256, GSMEM>>>(
        vals_ptr, wot_ptr, bo, out, M, EMB, EMB);
}

// round 8
// speedup vs baseline: 1.3030x; 1.3030x over previous
#include <cuda_runtime.h>
#include <cstdint>

// ---------------------------------------------------------------------------
//   q [4,2048,1024], c [4,2048,1024], W_kv [1024,2048], b_kv [2048],
//   W_o [1024,1024], b_o [1024] -> out [4,2048,1024] fp32
// kv row layout per (b,s): head h -> K at cols h*128..+63, V at h*128+64..+127
// ---------------------------------------------------------------------------

#define BATCH 4
#define SEQ   2048
#define EMB   1024
#define NH    16
#define HD    64

__device__ float g_kv[(size_t)BATCH * SEQ * 2 * EMB];    // 64 MB
__device__ float g_vals[(size_t)BATCH * SEQ * EMB];      // 32 MB
__device__ float g_wkvt[(size_t)2 * EMB * EMB];          // 8 MB  W_kv^T [2048,1024]
__device__ float g_wot[(size_t)EMB * EMB];               // 4 MB  W_o^T  [1024,1024]

__device__ __forceinline__ uint32_t pack2(float lo, float hi) {
    uint32_t r;   // d.hi = first src, d.lo = second src
    asm("cvt.rn.f16x2.f32 %0, %1, %2;" : "=r"(r) : "f"(hi), "f"(lo));
    return r;
}
__device__ __forceinline__ float ex2f(float x) {
    float y;
    asm("ex2.approx.f32 %0, %1;" : "=f"(y) : "f"(x));
    return y;
}

// m16n8k16 fp16 MMA, fp32 accumulate.
// A frag: a0=(g,2qd:2qd+1) a1=(g+8,same) a2=(g,2qd+8:+9) a3=(g+8,same)
// B frag: b0=(k 2qd:2qd+1, n g) b1=(k 2qd+8:+9, n g)
// C frag: c0=(g,2qd) c1=(g,2qd+1) c2=(g+8,2qd) c3=(g+8,2qd+1)
#define MMA_F16(d, a, b0v, b1v)                                             \
    asm volatile("mma.sync.aligned.m16n8k16.row.col.f32.f16.f16.f32 "       \
        "{%0,%1,%2,%3}, {%4,%5,%6,%7}, {%8,%9}, {%0,%1,%2,%3};"             \
        : "+f"((d)[0]), "+f"((d)[1]), "+f"((d)[2]), "+f"((d)[3])            \
        : "r"((a)[0]), "r"((a)[1]), "r"((a)[2]), "r"((a)[3]),               \
          "r"(b0v), "r"(b1v))

// ======================= weight transpose ===================================
__global__ __launch_bounds__(256)
void transpose_kernel(const float* __restrict__ in, float* __restrict__ out,
                      int R, int C)
{
    __shared__ float t[32][33];
    int bx = blockIdx.x * 32, by = blockIdx.y * 32;
    int x = bx + threadIdx.x;
    #pragma unroll
    for (int i = 0; i < 32; i += 8)
        t[threadIdx.y + i][threadIdx.x] = in[(size_t)(by + threadIdx.y + i) * C + x];
    __syncthreads();
    int ox = by + threadIdx.x;
    #pragma unroll
    for (int i = 0; i < 32; i += 8)
        out[(size_t)(bx + threadIdx.y + i) * R + ox] = t[threadIdx.x][threadIdx.y + i];
}

// ======================= fp16-mma GEMM + bias (2 CTA/SM) ====================
// C[M,N] = A[M,K] @ Bt[N,K]^T + bias[N].  Block 128x128, 8 warps.
// smem: half2-packed rows, stride 20 words (16 data + 4 pad; banks 20g+qd
// all-distinct for fragment loads). Double-buffered, K chunk 32.
#define GST 20
#define GASZ (128 * GST)          // 2560 words per buffer
#define GSMEM (4 * GASZ * 4)      // 40960 bytes

__global__ __launch_bounds__(256, 2)
void gemm_mma_f16(const float* __restrict__ A, const float* __restrict__ Bt,
                  const float* __restrict__ bias, float* __restrict__ C,
                  int M, int N, int K)
{
    extern __shared__ uint32_t gsm[];
    // layout: Ab[2][GASZ] | Bb[2][GASZ]

    const int tid  = threadIdx.x;
    const int w    = tid >> 5;
    const int lane = tid & 31;
    const int g    = lane >> 2;
    const int qd   = lane & 3;
    const int brow = blockIdx.y * 128;
    const int bcol = blockIdx.x * 128;

    float acc[16][4];
    #pragma unroll
    for (int j = 0; j < 16; j++)
        #pragma unroll
        for (int e = 0; e < 4; e++) acc[j][e] = 0.f;

    const int lr = tid >> 1;          // 0..127
    const int lc = (tid & 1) * 16;    // 0 or 16

    float4 Ar[4], Br[4];
    auto LOADT = [&](int k0) {
        const float* ap = A  + (size_t)(brow + lr) * K + k0 + lc;
        const float* bp = Bt + (size_t)(bcol + lr) * K + k0 + lc;
        #pragma unroll
        for (int i = 0; i < 4; i++) {
            Ar[i] = *(const float4*)(ap + 4 * i);
            Br[i] = *(const float4*)(bp + 4 * i);
        }
    };
    auto STORET = [&](int p) {
        uint32_t* Ab = gsm + p * GASZ;
        uint32_t* Bb = gsm + 2 * GASZ + p * GASZ;
        float ax[16] = {Ar[0].x,Ar[0].y,Ar[0].z,Ar[0].w, Ar[1].x,Ar[1].y,Ar[1].z,Ar[1].w,
                        Ar[2].x,Ar[2].y,Ar[2].z,Ar[2].w, Ar[3].x,Ar[3].y,Ar[3].z,Ar[3].w};
        float bx[16] = {Br[0].x,Br[0].y,Br[0].z,Br[0].w, Br[1].x,Br[1].y,Br[1].z,Br[1].w,
                        Br[2].x,Br[2].y,Br[2].z,Br[2].w, Br[3].x,Br[3].y,Br[3].z,Br[3].w};
        int base = lr * GST + (tid & 1) * 8;
        #pragma unroll
        for (int i = 0; i < 8; i++) {
            Ab[base + i] = pack2(ax[2 * i], ax[2 * i + 1]);
            Bb[base + i] = pack2(bx[2 * i], bx[2 * i + 1]);
        }
    };

    LOADT(0);
    STORET(0);
    __syncthreads();

    const int arow0 = (16 * w + g) * GST;
    const int arow1 = arow0 + 8 * GST;

    const int NCH = K / 32;
    for (int ch = 0; ch < NCH; ch++) {
        const int p = ch & 1;
        if (ch + 1 < NCH) LOADT((ch + 1) * 32);

        const uint32_t* Ab = gsm + p * GASZ;
        const uint32_t* Bb = gsm + 2 * GASZ + p * GASZ;

        #pragma unroll
        for (int ks = 0; ks < 2; ks++) {        // two k16 groups per chunk
            uint32_t af[4];
            af[0] = Ab[arow0 + 8 * ks + qd];
            af[1] = Ab[arow1 + 8 * ks + qd];
            af[2] = Ab[arow0 + 8 * ks + qd + 4];
            af[3] = Ab[arow1 + 8 * ks + qd + 4];
            #pragma unroll
            for (int j = 0; j < 16; j++) {
                const uint32_t* brow_p = &Bb[(8 * j + g) * GST + 8 * ks + qd];
                MMA_F16(acc[j], af, brow_p[0], brow_p[4]);
            }
        }

        if (ch + 1 < NCH) STORET(1 - p);
        __syncthreads();
    }

    const int row0 = brow + 16 * w + g;
    const int row1 = row0 + 8;
    #pragma unroll
    for (int j = 0; j < 16; j++) {
        int col = bcol + 8 * j + 2 * qd;
        float b0 = __ldg(bias + col), b1 = __ldg(bias + col + 1);
        float2 x0 = make_float2(acc[j][0] + b0, acc[j][1] + b1);
        float2 x1 = make_float2(acc[j][2] + b0, acc[j][3] + b1);
        *(float2*)&C[(size_t)row0 * N + col] = x0;
        *(float2*)&C[(size_t)row1 * N + col] = x1;
    }
}

// ======================= Flash attention (fp16 mma, no P shuffles) ==========
// Block: 128-row Q tile of one (b,h). 8 warps; warp w owns rows w*16..+15.
// KV tile 32 rows, double-buffered.
// K smem:  [32 kv][64 hd] halves, row stride 36 words (banks 4g+qd, CF).
// V smem:  transposed kv-pairs: word (hd, p) = half2(V[2p][hd], V[2p+1][hd]),
//          row stride 20 words (banks 20g+qd, CF).
#define KST 36
#define KSZ (32 * KST)            // 1152 words
#define VST 20
#define VSZ (64 * VST)            // 1280 words
#define STG (KSZ + VSZ)           // 2432 words = 9728 B per stage

__global__ __launch_bounds__(256, 2)
void flash_attn_mma(const float* __restrict__ q,
                    const float* __restrict__ kv,
                    float* __restrict__ vals)
{
    extern __shared__ uint32_t smx[];

    const int tid  = threadIdx.x;
    const int w    = tid >> 5;
    const int lane = tid & 31;
    const int g    = lane >> 2;
    const int qd   = lane & 3;
    const int b    = blockIdx.y >> 4;
    const int h    = blockIdx.y & 15;
    const int q0   = blockIdx.x * 128;

    const size_t qrow0 = (size_t)b * SEQ + q0 + w * 16;
    const float* qb = q + qrow0 * EMB + h * HD;

    // Q fragments (4 k16 groups), scaled by 1/8*log2(e), fp16-packed
    const float QS = 0.125f * 1.4426950408889634f;
    uint32_t qf[4][4];
    #pragma unroll
    for (int kk = 0; kk < 4; kk++) {
        float2 v;
        v = *(const float2*)(qb + (size_t)g * EMB + 16 * kk + 2 * qd);
        qf[kk][0] = pack2(v.x * QS, v.y * QS);
        v = *(const float2*)(qb + (size_t)(g + 8) * EMB + 16 * kk + 2 * qd);
        qf[kk][1] = pack2(v.x * QS, v.y * QS);
        v = *(const float2*)(qb + (size_t)g * EMB + 16 * kk + 2 * qd + 8);
        qf[kk][2] = pack2(v.x * QS, v.y * QS);
        v = *(const float2*)(qb + (size_t)(g + 8) * EMB + 16 * kk + 2 * qd + 8);
        qf[kk][3] = pack2(v.x * QS, v.y * QS);
    }

    float oa[8][4];
    #pragma unroll
    for (int j = 0; j < 8; j++)
        #pragma unroll
        for (int e = 0; e < 4; e++) oa[j][e] = 0.f;
    float m0 = -1e30f, m1 = -1e30f, l0 = 0.f, l1 = 0.f;

    const float* kb = kv + (size_t)b * SEQ * (2 * EMB) + h * (2 * HD);

    // loader roles: warps 0-3 load K; warps 4-7 load V (transposed pairs)
    const int krow = tid & 31;             // K: kv row
    const int kseg = (tid >> 5) & 3;       // K: 16-float hd segment (0..3)
    const int uu   = tid - 128;
    const int vp   = uu & 15;              // V: kv pair index 0..15
    const int vseg = uu >> 4;              // V: 8-float hd segment 0..7

    float4 pv4[4];
    auto LOADT = [&](int it) {
        if (tid < 128) {
            const float* base = kb + (size_t)(it * 32 + krow) * (2 * EMB) + kseg * 16;
            #pragma unroll
            for (int i = 0; i < 4; i++) pv4[i] = *(const float4*)(base + 4 * i);
        } else {
            const float* r0p = kb + (size_t)(it * 32 + 2 * vp) * (2 * EMB) + HD + vseg * 8;
            const float* r1p = r0p + 2 * EMB;
            pv4[0] = *(const float4*)r0p;
            pv4[1] = *(const float4*)(r0p + 4);
            pv4[2] = *(const float4*)r1p;
            pv4[3] = *(const float4*)(r1p + 4);
        }
    };
    auto STORET = [&](int s) {
        uint32_t* Ks = smx + s * STG;
        uint32_t* Vs = Ks + KSZ;
        if (tid < 128) {
            float x[16] = {pv4[0].x,pv4[0].y,pv4[0].z,pv4[0].w,
                           pv4[1].x,pv4[1].y,pv4[1].z,pv4[1].w,
                           pv4[2].x,pv4[2].y,pv4[2].z,pv4[2].w,
                           pv4[3].x,pv4[3].y,pv4[3].z,pv4[3].w};
            int base = krow * KST + kseg * 8;
            #pragma unroll
            for (int i = 0; i < 8; i++)
                Ks[base + i] = pack2(x[2 * i], x[2 * i + 1]);
        } else {
            float x0[8] = {pv4[0].x,pv4[0].y,pv4[0].z,pv4[0].w,
                           pv4[1].x,pv4[1].y,pv4[1].z,pv4[1].w};
            float x1[8] = {pv4[2].x,pv4[2].y,pv4[2].z,pv4[2].w,
                           pv4[3].x,pv4[3].y,pv4[3].z,pv4[3].w};
            #pragma unroll
            for (int i = 0; i < 8; i++)
                Vs[(8 * vseg + i) * VST + vp] = pack2(x0[i], x1[i]);
        }
    };

    LOADT(0);
    STORET(0);
    __syncthreads();

    const int NIT = SEQ / 32;
    for (int it = 0; it < NIT; it++) {
        const int s = it & 1;
        const uint32_t* Ks = smx + s * STG;
        const uint32_t* Vs = Ks + KSZ;

        // ---- S = Q @ K^T : 4 kv n-tiles x 4 k16 groups ----
        float sa[4][4];
        #pragma unroll
        for (int j = 0; j < 4; j++)
            #pragma unroll
            for (int e = 0; e < 4; e++) sa[j][e] = 0.f;
        #pragma unroll
        for (int kk = 0; kk < 4; kk++) {
            #pragma unroll
            for (int j = 0; j < 4; j++) {
                const uint32_t* kp = &Ks[(8 * j + g) * KST + 8 * kk + qd];
                MMA_F16(sa[j], qf[kk], kp[0], kp[4]);
            }
        }

        // prefetch next KV tile
        if (it < NIT - 1) LOADT(it + 1);

        // ---- online softmax in exp2 domain ----
        float tm0 = -1e30f, tm1 = -1e30f;
        #pragma unroll
        for (int j = 0; j < 4; j++) {
            tm0 = fmaxf(tm0, fmaxf(sa[j][0], sa[j][1]));
            tm1 = fmaxf(tm1, fmaxf(sa[j][2], sa[j][3]));
        }
        tm0 = fmaxf(tm0, __shfl_xor_sync(0xffffffffu, tm0, 1));
        tm0 = fmaxf(tm0, __shfl_xor_sync(0xffffffffu, tm0, 2));
        tm1 = fmaxf(tm1, __shfl_xor_sync(0xffffffffu, tm1, 1));
        tm1 = fmaxf(tm1, __shfl_xor_sync(0xffffffffu, tm1, 2));
        float mn0 = fmaxf(m0, tm0), mn1 = fmaxf(m1, tm1);
        float al0 = ex2f(m0 - mn0), al1 = ex2f(m1 - mn1);
        m0 = mn0; m1 = mn1;

        float p[4][4];
        float sum0 = 0.f, sum1 = 0.f;
        #pragma unroll
        for (int j = 0; j < 4; j++) {
            p[j][0] = ex2f(sa[j][0] - mn0);
            p[j][1] = ex2f(sa[j][1] - mn0);
            p[j][2] = ex2f(sa[j][2] - mn1);
            p[j][3] = ex2f(sa[j][3] - mn1);
            sum0 += p[j][0] + p[j][1];
            sum1 += p[j][2] + p[j][3];
        }
        l0 = l0 * al0 + sum0;
        l1 = l1 * al1 + sum1;
        #pragma unroll
        for (int j = 0; j < 8; j++) {
            oa[j][0] *= al0; oa[j][1] *= al0;
            oa[j][2] *= al1; oa[j][3] *= al1;
        }

        // ---- O += P @ V : C-frag of S == A-frag of P (no shuffles) ----
        #pragma unroll
        for (int j2 = 0; j2 < 2; j2++) {       // k16 group = S tiles 2j2,2j2+1
            uint32_t af[4];
            af[0] = pack2(p[2 * j2][0],     p[2 * j2][1]);
            af[1] = pack2(p[2 * j2][2],     p[2 * j2][3]);
            af[2] = pack2(p[2 * j2 + 1][0], p[2 * j2 + 1][1]);
            af[3] = pack2(p[2 * j2 + 1][2], p[2 * j2 + 1][3]);
            #pragma unroll
            for (int j = 0; j < 8; j++) {
                const uint32_t* vpnt = &Vs[(8 * j + g) * VST + 8 * j2 + qd];
                MMA_F16(oa[j], af, vpnt[0], vpnt[4]);
            }
        }

        if (it < NIT - 1) STORET(1 - s);
        __syncthreads();
    }

    // ---- epilogue ----
    l0 += __shfl_xor_sync(0xffffffffu, l0, 1);
    l0 += __shfl_xor_sync(0xffffffffu, l0, 2);
    l1 += __shfl_xor_sync(0xffffffffu, l1, 1);
    l1 += __shfl_xor_sync(0xffffffffu, l1, 2);
    float li0 = 1.0f / l0, li1 = 1.0f / l1;

    float* ob = vals + qrow0 * EMB + h * HD;
    #pragma unroll
    for (int j = 0; j < 8; j++) {
        float2 x0 = make_float2(oa[j][0] * li0, oa[j][1] * li0);
        float2 x1 = make_float2(oa[j][2] * li1, oa[j][3] * li1);
        *(float2*)&ob[(size_t)g * EMB + 8 * j + 2 * qd]       = x0;
        *(float2*)&ob[(size_t)(g + 8) * EMB + 8 * j + 2 * qd] = x1;
    }
}

// ======================= launch =============================================
extern "C" void kernel_launch(void* const* d_in, const int* in_sizes, int n_in,
                              void* d_out, int out_size)
{
    const float* q_in = (const float*)d_in[0];
    const float* c_in = (const float*)d_in[1];
    const float* Wkv  = (const float*)d_in[2];
    const float* bkv  = (const float*)d_in[3];
    const float* Wo   = (const float*)d_in[4];
    const float* bo   = (const float*)d_in[5];
    float* out = (float*)d_out;

    float *kv_ptr, *vals_ptr, *wkvt_ptr, *wot_ptr;
    cudaGetSymbolAddress((void**)&kv_ptr,  g_kv);
    cudaGetSymbolAddress((void**)&vals_ptr, g_vals);
    cudaGetSymbolAddress((void**)&wkvt_ptr, g_wkvt);
    cudaGetSymbolAddress((void**)&wot_ptr,  g_wot);

    const int M = BATCH * SEQ;             // 8192

    // 0) transpose weights
    transpose_kernel<<<dim3((2 * EMB) / 32, EMB / 32), dim3(32, 8)>>>(
        Wkv, wkvt_ptr, EMB, 2 * EMB);
    transpose_kernel<<<dim3(EMB / 32, EMB / 32), dim3(32, 8)>>>(
        Wo, wot_ptr, EMB, EMB);

    // 1) kv = c @ W_kv + b_kv         [8192, 2048]
    cudaFuncSetAttribute(gemm_mma_f16,
                         cudaFuncAttributeMaxDynamicSharedMemorySize, GSMEM);
    gemm_mma_f16<<<dim3((2 * EMB) / 128, M / 128), 256, GSMEM>>>(
        c_in, wkvt_ptr, bkv, kv_ptr, M, 2 * EMB, EMB);

    // 2) flash attention -> values    [8192, 1024]
    size_t smem = (size_t)2 * STG * sizeof(uint32_t);    // 19456 B
    cudaFuncSetAttribute(flash_attn_mma,
                         cudaFuncAttributeMaxDynamicSharedMemorySize, (int)smem);
    flash_attn_mma<<<dim3(SEQ / 128, BATCH * NH), 256, smem>>>(
        q_in, kv_ptr, vals_ptr);

    // 3) out = values @ W_o + b_o     [8192, 1024]
    gemm_mma_f16<<<dim3(EMB / 128, M / 128), 256, GSMEM>>>(
        vals_ptr, wot_ptr, bo, out, M, EMB, EMB);
}

// round 9
// speedup vs baseline: 2.2013x; 1.6895x over previous
#include <cuda_runtime.h>
#include <cuda_fp16.h>
#include <cstdint>

// ---------------------------------------------------------------------------
//   q [4,2048,1024], c [4,2048,1024], W_kv [1024,2048], b_kv [2048],
//   W_o [1024,1024], b_o [1024] -> out [4,2048,1024] fp32
// ---------------------------------------------------------------------------

#define BATCH 4
#define SEQ   2048
#define EMB   1024
#define NH    16
#define HD    64

// fp16 staging buffers (half2 words)
__device__ uint4 g_c16_[(size_t)8192 * 512 / 4];        // c fp16 [8192][512w]
__device__ uint4 g_wkvt16_[(size_t)2048 * 512 / 4];     // W_kv^T fp16 [2048][512w]
__device__ uint4 g_wot16_[(size_t)1024 * 512 / 4];      // W_o^T fp16 [1024][512w]
__device__ uint4 g_k16_[(size_t)64 * 2048 * 32 / 4];    // K fp16 [b*h][s][32w]
__device__ uint4 g_v16_[(size_t)64 * 64 * 1024 / 4];    // V^T pairs [b*h][hd][1024w]
__device__ uint4 g_vals16_[(size_t)8192 * 512 / 4];     // attn out fp16 [8192][512w]

__device__ __forceinline__ uint32_t pack2(float lo, float hi) {
    uint32_t r;
    asm("cvt.rn.f16x2.f32 %0, %1, %2;" : "=r"(r) : "f"(hi), "f"(lo));
    return r;
}
__device__ __forceinline__ float ex2f(float x) {
    float y;
    asm("ex2.approx.f32 %0, %1;" : "=f"(y) : "f"(x));
    return y;
}
__device__ __forceinline__ uint32_t smem_u32(const void* p) {
    uint32_t a;
    asm("{ .reg .u64 t; cvta.to.shared.u64 t, %1; cvt.u32.u64 %0, t; }"
        : "=r"(a) : "l"(p));
    return a;
}
#define CP16(d, s) \
    asm volatile("cp.async.ca.shared.global [%0], [%1], 16;" :: "r"(d), "l"(s) : "memory")
#define CP_COMMIT() asm volatile("cp.async.commit_group;" ::: "memory")
#define CP_WAIT0()  asm volatile("cp.async.wait_group 0;" ::: "memory")

#define MMA_F16(d, a, b0v, b1v)                                             \
    asm volatile("mma.sync.aligned.m16n8k16.row.col.f32.f16.f16.f32 "       \
        "{%0,%1,%2,%3}, {%4,%5,%6,%7}, {%8,%9}, {%0,%1,%2,%3};"             \
        : "+f"((d)[0]), "+f"((d)[1]), "+f"((d)[2]), "+f"((d)[3])            \
        : "r"((a)[0]), "r"((a)[1]), "r"((a)[2]), "r"((a)[3]),               \
          "r"(b0v), "r"(b1v))

// ======================= prologue kernels ===================================
// fp32 [R,C] -> fp16 transposed [C,R]
__global__ __launch_bounds__(256)
void transpose_half(const float* __restrict__ in, __half* __restrict__ out,
                    int R, int C)
{
    __shared__ float t[32][33];
    int bx = blockIdx.x * 32, by = blockIdx.y * 32;
    int x = bx + threadIdx.x;
    #pragma unroll
    for (int i = 0; i < 32; i += 8)
        t[threadIdx.y + i][threadIdx.x] = in[(size_t)(by + threadIdx.y + i) * C + x];
    __syncthreads();
    int ox = by + threadIdx.x;
    #pragma unroll
    for (int i = 0; i < 32; i += 8)
        out[(size_t)(bx + threadIdx.y + i) * R + ox] =
            __float2half(t[threadIdx.x][threadIdx.y + i]);
}

// fp32 -> fp16 packed (n float4 -> n uint2)
__global__ __launch_bounds__(256)
void convert_half(const float4* __restrict__ in, uint2* __restrict__ out)
{
    size_t i = (size_t)blockIdx.x * 256 + threadIdx.x;
    float4 v = in[i];
    out[i] = make_uint2(pack2(v.x, v.y), pack2(v.z, v.w));
}

// ======================= fp16 GEMM (cp.async, warp tile 32x64) ==============
// C = A16[M,Kh] @ B16[N,Kh]^T + bias.  Block 128x128, 8 warps (4x2 grid).
// smem row: 16 data words + 4 pad = 80B. K chunk = 32 halfs.
// mode 0: fp32 out + bias.   mode 1: kv epilogue (K fp16 rows, V^T pairs).
#define GST 20
#define GBUF 2560                 // 128*GST words per operand buffer
#define GSTAGE (2 * GBUF)         // A + B, one stage (words)
#define GSMEM (2 * GSTAGE * 4)    // 40960 bytes

__global__ __launch_bounds__(256, 2)
void gemm16(const uint32_t* __restrict__ A16, const uint32_t* __restrict__ B16,
            const float* __restrict__ bias, float* __restrict__ Cout,
            uint32_t* __restrict__ k16, uint32_t* __restrict__ v16,
            int M, int N, int K, int mode)
{
    extern __shared__ uint32_t gsm[];
    const uint32_t smb = smem_u32(gsm);

    const int tid  = threadIdx.x;
    const int w    = tid >> 5;
    const int lane = tid & 31;
    const int g    = lane >> 2;
    const int qd   = lane & 3;
    const int wm   = w >> 1;            // 0..3 (32-row strip)
    const int wn   = w & 1;             // 0..1 (64-col strip)
    const int brow = blockIdx.y * 128;
    const int bcol = blockIdx.x * 128;
    const int KW   = K >> 1;            // words per row

    float acc[2][8][4];
    #pragma unroll
    for (int mi = 0; mi < 2; mi++)
        #pragma unroll
        for (int j = 0; j < 8; j++)
            #pragma unroll
            for (int e = 0; e < 4; e++) acc[mi][j][e] = 0.f;

    const int lr = tid >> 1;
    const int lq = tid & 1;

    auto ISSUE = [&](int ch, int s) {
        const uint32_t* asrc = A16 + (size_t)(brow + lr) * KW + ch * 16 + lq * 8;
        const uint32_t* bsrc = B16 + (size_t)(bcol + lr) * KW + ch * 16 + lq * 8;
        uint32_t ad = smb + s * (GSTAGE * 4) + lr * 80 + lq * 32;
        uint32_t bd = ad + GBUF * 4;
        CP16(ad, asrc);      CP16(ad + 16, asrc + 4);
        CP16(bd, bsrc);      CP16(bd + 16, bsrc + 4);
    };

    ISSUE(0, 0);
    CP_COMMIT();

    const int NCH = K / 32;
    for (int ch = 0; ch < NCH; ch++) {
        const int s = ch & 1;
        CP_WAIT0();
        __syncthreads();
        if (ch + 1 < NCH) { ISSUE(ch + 1, 1 - s); CP_COMMIT(); }

        const uint32_t* Ab = gsm + s * GSTAGE;
        const uint32_t* Bb = Ab + GBUF;

        #pragma unroll
        for (int ks = 0; ks < 2; ks++) {
            uint32_t af[2][4];
            #pragma unroll
            for (int mi = 0; mi < 2; mi++) {
                int r0 = (32 * wm + 16 * mi + g) * GST + 8 * ks + qd;
                af[mi][0] = Ab[r0];
                af[mi][1] = Ab[r0 + 8 * GST];
                af[mi][2] = Ab[r0 + 4];
                af[mi][3] = Ab[r0 + 8 * GST + 4];
            }
            #pragma unroll
            for (int j = 0; j < 8; j++) {
                const uint32_t* bp = &Bb[(64 * wn + 8 * j + g) * GST + 8 * ks + qd];
                uint32_t b0 = bp[0], b1 = bp[4];
                MMA_F16(acc[0][j], af[0], b0, b1);
                MMA_F16(acc[1][j], af[1], b0, b1);
            }
        }
    }
    __syncthreads();

    if (mode == 0) {
        #pragma unroll
        for (int mi = 0; mi < 2; mi++) {
            const int row0 = brow + 32 * wm + 16 * mi + g;
            #pragma unroll
            for (int j = 0; j < 8; j++) {
                int col = bcol + 64 * wn + 8 * j + 2 * qd;
                float b0 = __ldg(bias + col), b1 = __ldg(bias + col + 1);
                float2 x0 = make_float2(acc[mi][j][0] + b0, acc[mi][j][1] + b1);
                float2 x1 = make_float2(acc[mi][j][2] + b0, acc[mi][j][3] + b1);
                *(float2*)&Cout[(size_t)row0 * N + col] = x0;
                *(float2*)&Cout[(size_t)(row0 + 8) * N + col] = x1;
            }
        }
    } else {
        // kv epilogue: block = one head. wn=0 -> K half, wn=1 -> V half.
        const int bh = (brow >> 11) * NH + (bcol >> 7);
        const int sb = brow & 2047;
        #pragma unroll
        for (int mi = 0; mi < 2; mi++) {
            const int s0 = sb + 32 * wm + 16 * mi;
            #pragma unroll
            for (int j = 0; j < 8; j++) {
                if (wn == 0) {
                    int col = 8 * j + 2 * qd;
                    float b0 = __ldg(bias + bcol + col);
                    float b1 = __ldg(bias + bcol + col + 1);
                    size_t base = ((size_t)bh * SEQ + s0 + g) * 32 + 4 * j + qd;
                    k16[base] = pack2(acc[mi][j][0] + b0, acc[mi][j][1] + b1);
                    k16[base + 8 * 32] =
                        pack2(acc[mi][j][2] + b0, acc[mi][j][3] + b1);
                } else {
                    int hd = 8 * j + 2 * qd;
                    float b0 = __ldg(bias + bcol + 64 + hd);
                    float b1 = __ldg(bias + bcol + 64 + hd + 1);
                    int grp = s0 >> 4;
                    size_t base = ((size_t)bh * 64 + hd) * 1024 + grp * 8 + g;
                    v16[base] = pack2(acc[mi][j][0] + b0, acc[mi][j][2] + b0);
                    v16[base + 1024] =
                        pack2(acc[mi][j][1] + b1, acc[mi][j][3] + b1);
                }
            }
        }
    }
}

// ======================= Flash attention (fp16, cp.async, KV tile 64) =======
// Block: 128-row Q tile of one (b,h). 8 warps; warp w owns rows w*16..+15.
// K smem: position p holds kv row tau(p) (tau(2i)=i, tau(2i+1)=i+8 per
// 16-group) so GEMM's (r,r+8) V pairs line up with P column pairs.
// Rows: 32 data words + 4 pad = 144B stride (banks 4g+qd, conflict-free).
#define KVST 36
#define AKSZ (64 * KVST)          // 2304 words
#define ASTG (2 * AKSZ)           // K + V per stage (words)
#define ASMEM (2 * ASTG * 4)      // 36864 bytes

__global__ __launch_bounds__(256, 2)
void flash_attn_mma(const float* __restrict__ q,
                    const uint32_t* __restrict__ k16,
                    const uint32_t* __restrict__ v16,
                    uint32_t* __restrict__ vals16)
{
    extern __shared__ uint32_t smx[];
    const uint32_t smb = smem_u32(smx);

    const int tid  = threadIdx.x;
    const int w    = tid >> 5;
    const int lane = tid & 31;
    const int g    = lane >> 2;
    const int qd   = lane & 3;
    const int b    = blockIdx.y >> 4;
    const int h    = blockIdx.y & 15;
    const int q0   = blockIdx.x * 128;
    const int bh   = b * NH + h;

    const size_t qrow0 = (size_t)b * SEQ + q0 + w * 16;
    const float* qb = q + qrow0 * EMB + h * HD;

    // Q fragments (4 k16 groups), scaled by 1/8*log2(e), fp16-packed
    const float QS = 0.125f * 1.4426950408889634f;
    uint32_t qf[4][4];
    #pragma unroll
    for (int kk = 0; kk < 4; kk++) {
        float2 v;
        v = *(const float2*)(qb + (size_t)g * EMB + 16 * kk + 2 * qd);
        qf[kk][0] = pack2(v.x * QS, v.y * QS);
        v = *(const float2*)(qb + (size_t)(g + 8) * EMB + 16 * kk + 2 * qd);
        qf[kk][1] = pack2(v.x * QS, v.y * QS);
        v = *(const float2*)(qb + (size_t)g * EMB + 16 * kk + 2 * qd + 8);
        qf[kk][2] = pack2(v.x * QS, v.y * QS);
        v = *(const float2*)(qb + (size_t)(g + 8) * EMB + 16 * kk + 2 * qd + 8);
        qf[kk][3] = pack2(v.x * QS, v.y * QS);
    }

    float oa[8][4];
    #pragma unroll
    for (int j = 0; j < 8; j++)
        #pragma unroll
        for (int e = 0; e < 4; e++) oa[j][e] = 0.f;
    float m0 = -1e30f, m1 = -1e30f, l0 = 0.f, l1 = 0.f;

    const uint32_t* kbase = k16 + (size_t)bh * SEQ * 32;
    const uint32_t* vbase = v16 + (size_t)bh * 64 * 1024;

    // loaders (cp.async, no data registers)
    const int p    = tid >> 2;            // K smem position 0..63
    const int seg  = tid & 3;
    const int tau  = (p & ~15) + ((p & 15) >> 1) + ((p & 1) << 3);
    const int vhd  = tid >> 2;            // V hd row 0..63
    const int vseg = tid & 3;

    auto ISSUE = [&](int it, int s) {
        const uint32_t* ks = kbase + (size_t)(it * 64 + tau) * 32 + seg * 8;
        uint32_t kd = smb + s * (ASTG * 4) + p * 144 + seg * 32;
        CP16(kd, ks); CP16(kd + 16, ks + 4);
        const uint32_t* vs = vbase + (size_t)vhd * 1024 + it * 32 + vseg * 8;
        uint32_t vd = smb + s * (ASTG * 4) + AKSZ * 4 + vhd * 144 + vseg * 32;
        CP16(vd, vs); CP16(vd + 16, vs + 4);
    };

    ISSUE(0, 0);
    CP_COMMIT();

    const int NIT = SEQ / 64;
    for (int it = 0; it < NIT; it++) {
        const int s = it & 1;
        CP_WAIT0();
        __syncthreads();
        if (it + 1 < NIT) { ISSUE(it + 1, 1 - s); CP_COMMIT(); }

        const uint32_t* Ks = smx + s * ASTG;
        const uint32_t* Vs = Ks + AKSZ;

        // ---- S = Q @ K^T : 8 n-tiles x 4 k16 groups ----
        float sa[8][4];
        #pragma unroll
        for (int j = 0; j < 8; j++)
            #pragma unroll
            for (int e = 0; e < 4; e++) sa[j][e] = 0.f;
        #pragma unroll
        for (int kk = 0; kk < 4; kk++) {
            #pragma unroll
            for (int j = 0; j < 8; j++) {
                const uint32_t* kp = &Ks[(8 * j + g) * KVST + 8 * kk + qd];
                MMA_F16(sa[j], qf[kk], kp[0], kp[4]);
            }
        }

        // ---- online softmax in exp2 domain ----
        float tm0 = -1e30f, tm1 = -1e30f;
        #pragma unroll
        for (int j = 0; j < 8; j++) {
            tm0 = fmaxf(tm0, fmaxf(sa[j][0], sa[j][1]));
            tm1 = fmaxf(tm1, fmaxf(sa[j][2], sa[j][3]));
        }
        tm0 = fmaxf(tm0, __shfl_xor_sync(0xffffffffu, tm0, 1));
        tm0 = fmaxf(tm0, __shfl_xor_sync(0xffffffffu, tm0, 2));
        tm1 = fmaxf(tm1, __shfl_xor_sync(0xffffffffu, tm1, 1));
        tm1 = fmaxf(tm1, __shfl_xor_sync(0xffffffffu, tm1, 2));
        float mn0 = fmaxf(m0, tm0), mn1 = fmaxf(m1, tm1);
        float al0 = ex2f(m0 - mn0), al1 = ex2f(m1 - mn1);
        m0 = mn0; m1 = mn1;

        float sum0 = 0.f, sum1 = 0.f;
        #pragma unroll
        for (int j = 0; j < 8; j++) {
            sa[j][0] = ex2f(sa[j][0] - mn0);
            sa[j][1] = ex2f(sa[j][1] - mn0);
            sa[j][2] = ex2f(sa[j][2] - mn1);
            sa[j][3] = ex2f(sa[j][3] - mn1);
            sum0 += sa[j][0] + sa[j][1];
            sum1 += sa[j][2] + sa[j][3];
        }
        l0 = l0 * al0 + sum0;
        l1 = l1 * al1 + sum1;
        #pragma unroll
        for (int j = 0; j < 8; j++) {
            oa[j][0] *= al0; oa[j][1] *= al0;
            oa[j][2] *= al1; oa[j][3] *= al1;
        }

        // ---- O += P @ V : C-frag of S == A-frag of P (no shuffles) ----
        #pragma unroll
        for (int j2 = 0; j2 < 4; j2++) {
            uint32_t af[4];
            af[0] = pack2(sa[2 * j2][0],     sa[2 * j2][1]);
            af[1] = pack2(sa[2 * j2][2],     sa[2 * j2][3]);
            af[2] = pack2(sa[2 * j2 + 1][0], sa[2 * j2 + 1][1]);
            af[3] = pack2(sa[2 * j2 + 1][2], sa[2 * j2 + 1][3]);
            #pragma unroll
            for (int j = 0; j < 8; j++) {
                const uint32_t* vp = &Vs[(8 * j + g) * KVST + 8 * j2 + qd];
                MMA_F16(oa[j], af, vp[0], vp[4]);
            }
        }
    }

    // ---- epilogue: normalize, write fp16 vals ----
    l0 += __shfl_xor_sync(0xffffffffu, l0, 1);
    l0 += __shfl_xor_sync(0xffffffffu, l0, 2);
    l1 += __shfl_xor_sync(0xffffffffu, l1, 1);
    l1 += __shfl_xor_sync(0xffffffffu, l1, 2);
    float li0 = 1.0f / l0, li1 = 1.0f / l1;

    #pragma unroll
    for (int j = 0; j < 8; j++) {
        size_t w0 = (qrow0 + g) * 512 + h * 32 + 4 * j + qd;
        size_t w1 = (qrow0 + g + 8) * 512 + h * 32 + 4 * j + qd;
        vals16[w0] = pack2(oa[j][0] * li0, oa[j][1] * li0);
        vals16[w1] = pack2(oa[j][2] * li1, oa[j][3] * li1);
    }
}

// ======================= launch =============================================
extern "C" void kernel_launch(void* const* d_in, const int* in_sizes, int n_in,
                              void* d_out, int out_size)
{
    const float* q_in = (const float*)d_in[0];
    const float* c_in = (const float*)d_in[1];
    const float* Wkv  = (const float*)d_in[2];
    const float* bkv  = (const float*)d_in[3];
    const float* Wo   = (const float*)d_in[4];
    const float* bo   = (const float*)d_in[5];
    float* out = (float*)d_out;

    uint32_t *c16, *wkvt16, *wot16, *k16, *v16, *vals16;
    cudaGetSymbolAddress((void**)&c16,    g_c16_);
    cudaGetSymbolAddress((void**)&wkvt16, g_wkvt16_);
    cudaGetSymbolAddress((void**)&wot16,  g_wot16_);
    cudaGetSymbolAddress((void**)&k16,    g_k16_);
    cudaGetSymbolAddress((void**)&v16,    g_v16_);
    cudaGetSymbolAddress((void**)&vals16, g_vals16_);

    const int M = BATCH * SEQ;             // 8192

    // 0) prologue: transposed fp16 weights + fp16 c
    transpose_half<<<dim3((2 * EMB) / 32, EMB / 32), dim3(32, 8)>>>(
        Wkv, (__half*)wkvt16, EMB, 2 * EMB);
    transpose_half<<<dim3(EMB / 32, EMB / 32), dim3(32, 8)>>>(
        Wo, (__half*)wot16, EMB, EMB);
    convert_half<<<(M * EMB) / 1024, 256>>>(
        (const float4*)c_in, (uint2*)c16);

    // 1) kv projection -> K fp16 + V^T pairs fp16
    cudaFuncSetAttribute(gemm16,
                         cudaFuncAttributeMaxDynamicSharedMemorySize, GSMEM);
    gemm16<<<dim3((2 * EMB) / 128, M / 128), 256, GSMEM>>>(
        c16, wkvt16, bkv, nullptr, k16, v16, M, 2 * EMB, EMB, 1);

    // 2) flash attention -> vals fp16
    cudaFuncSetAttribute(flash_attn_mma,
                         cudaFuncAttributeMaxDynamicSharedMemorySize, ASMEM);
    flash_attn_mma<<<dim3(SEQ / 128, BATCH * NH), 256, ASMEM>>>(
        q_in, k16, v16, vals16);

    // 3) out = vals @ W_o + b_o  (fp32 out)
    gemm16<<<dim3(EMB / 128, M / 128), 256, GSMEM>>>(
        vals16, wot16, bo, out, nullptr, nullptr, M, EMB, EMB, 0);
}